// round 14
// baseline (speedup 1.0000x reference)
#include <cuda_runtime.h>
#include <cuda_fp16.h>

#define NN 100000
#define NE 1600000
#define NE_PAD (NE + 3 * NN + 4)  // segments padded to multiples of 4 (+4 slack)
#define D  48
#define D2 24                     // half2 chunks per feature row (96B packed)
#define HOPS 10
#define SCAN_BLKS ((NN + 1023) / 1024)   // 98

// ---- scratch (static device globals; no runtime allocation allowed) ----
__device__ int     g_degi[NN];
__device__ float   g_norm[NN];
__device__ int     g_offs[NN + 1];
__device__ int     g_bsum[128];
__device__ int     g_cursor[NN];
__device__ __align__(16) int g_csrc[NE_PAD];            // CSR src by dst (pad = NN)
__device__ __align__(16) __half2 g_hnA[(NN + 1) * D2];  // h*norm ping (row NN zeros)
__device__ __align__(16) __half2 g_hnB[(NN + 1) * D2];  // h*norm pong
__device__ unsigned g_bars[4];                          // grid-barrier counters (ffn resets)

// ---- packed f32x2 helpers (FFMA2: PTX-only on sm_103a) ----
__device__ __forceinline__ unsigned long long pk2(float x) {
    unsigned long long r;
    asm("mov.b64 %0, {%1, %1};" : "=l"(r) : "f"(x));
    return r;
}
__device__ __forceinline__ void fma2(unsigned long long& d,
                                     unsigned long long a, unsigned long long b) {
    asm("fma.rn.f32x2 %0, %1, %2, %0;" : "+l"(d) : "l"(a), "l"(b));
}
__device__ __forceinline__ float2 up2(unsigned long long v) {
    float x, y;
    asm("mov.b64 {%0, %1}, %2;" : "=f"(x), "=f"(y) : "l"(v));
    return make_float2(x, y);
}

// software grid barrier; all blocks co-resident (occupancy-sized launches)
__device__ __forceinline__ void gbar(int slot, unsigned target) {
    __syncthreads();
    if (threadIdx.x == 0) {
        __threadfence();
        atomicAdd(&g_bars[slot], 1u);
        while (((volatile unsigned*)g_bars)[slot] < target) __nanosleep(32);
        __threadfence();
    }
    __syncthreads();
}

// ---------------------------------------------------------------------
// build1: phase A zero degrees; barrier; phase B histogram of dst
__global__ void __launch_bounds__(256) k_build1(const int* __restrict__ dst, int nb) {
    int gt = blockIdx.x * blockDim.x + threadIdx.x;
    int gs = nb * 256;
    for (int i = gt; i < NN; i += gs) g_degi[i] = 0;
    gbar(0, (unsigned)nb);
    for (int e = gt; e < NE; e += gs) atomicAdd(&g_degi[dst[e]], 1);
}

// scan_all: phase A block-local inclusive scan of padded degrees;
// barrier; phase B fix-up + norm + cursor (each block redundantly scans bsums)
__global__ void __launch_bounds__(1024) k_scan_all() {
    __shared__ int sh[1024];
    int tid = threadIdx.x;
    int i = blockIdx.x * 1024 + tid;
    sh[tid] = (i < NN) ? ((g_degi[i] + 3) & ~3) : 0;
    __syncthreads();
#pragma unroll
    for (int off = 1; off < 1024; off <<= 1) {
        int t = (tid >= off) ? sh[tid - off] : 0;
        __syncthreads();
        sh[tid] += t;
        __syncthreads();
    }
    int myinc = sh[tid];
    if (tid == 1023) g_bsum[blockIdx.x] = sh[1023];

    gbar(1, (unsigned)SCAN_BLKS);

    __shared__ int sb[128];
    int v = 0;
    if (tid < 128) {
        v = (tid < SCAN_BLKS) ? g_bsum[tid] : 0;
        sb[tid] = v;
    }
    __syncthreads();
#pragma unroll
    for (int off = 1; off < 128; off <<= 1) {
        int u = (tid < 128 && tid >= off) ? sb[tid - off] : 0;
        __syncthreads();
        if (tid < 128) sb[tid] += u;
        __syncthreads();
    }
    if (tid < 128) sb[tid] -= v;   // exclusive
    __syncthreads();

    if (i < NN) {
        int o_end = myinc + sb[blockIdx.x];   // inclusive end for node i
        g_offs[i + 1] = o_end;
        int deg = g_degi[i];
        int pad = (deg + 3) & ~3;
        int o = o_end - pad;                  // start offset
        g_cursor[i] = o;
        g_norm[i] = rsqrtf(fmaxf((float)deg, 1.0f));
        if (i == 0) g_offs[0] = 0;
    }
}

// build2: phase A scatter edges into CSR; barrier; phase B pad tails + init hn
__global__ void __launch_bounds__(256) k_build2(const int* __restrict__ src,
                                                const int* __restrict__ dst,
                                                const float2* __restrict__ feat,
                                                int nb) {
    int gt = blockIdx.x * blockDim.x + threadIdx.x;
    int gs = nb * 256;
    for (int e = gt; e < NE; e += gs) {
        int pos = atomicAdd(&g_cursor[dst[e]], 1);
        g_csrc[pos] = src[e];
    }
    gbar(2, (unsigned)nb);
    if (gt == 0) {   // prefetch/slack words at the very end
        g_csrc[NE_PAD - 4] = NN; g_csrc[NE_PAD - 3] = NN;
        g_csrc[NE_PAD - 2] = NN; g_csrc[NE_PAD - 1] = NN;
    }
    for (int i = gt; i < NN; i += gs) {
        int p = g_cursor[i];
        int e = g_offs[i + 1];
        for (; p < e; p++) g_csrc[p] = NN;
    }
    for (int i = gt; i < (NN + 1) * D2; i += gs) {
        int node = i / D2;
        if (node == NN) {
            g_hnA[i] = __floats2half2_rn(0.f, 0.f);
            g_hnB[i] = __floats2half2_rn(0.f, 0.f);
        } else {
            float n = g_norm[node];
            float2 f = feat[i];
            g_hnA[i] = __floats2half2_rn(f.x * n, f.y * n);
        }
    }
}

// One warp per destination node; lanes 0..23 own one half2 each of the
// packed 96B row. 4 independent row loads per iteration; fp32 accumulation;
// fused APPNP combine + renorm epilogue. RB: 0 = read A write B.
// (Exact R9 form — empirically the fastest gather variant.)
template <int LAST, int RB>
__global__ void __launch_bounds__(256) k_prop(const float2* __restrict__ feat,
                                              float2* __restrict__ out_r) {
    int gw = (blockIdx.x * blockDim.x + threadIdx.x) >> 5;
    if (gw >= NN) return;
    int lane = threadIdx.x & 31;
    bool act = lane < D2;
    int idx = act ? lane : 0;

    const __half2* __restrict__ hn = RB ? g_hnB : g_hnA;
    int beg = g_offs[gw];
    int end = g_offs[gw + 1];

    float sx = 0.f, sy = 0.f;
    for (int e = beg; e < end; e += 4) {
        int4 ss = __ldg((const int4*)&g_csrc[e]);
        __half2 v0 = __ldg(&hn[(size_t)ss.x * D2 + idx]);
        __half2 v1 = __ldg(&hn[(size_t)ss.y * D2 + idx]);
        __half2 v2 = __ldg(&hn[(size_t)ss.z * D2 + idx]);
        __half2 v3 = __ldg(&hn[(size_t)ss.w * D2 + idx]);
        float2 f0 = __half22float2(v0);
        float2 f1 = __half22float2(v1);
        float2 f2 = __half22float2(v2);
        float2 f3 = __half22float2(v3);
        sx += (f0.x + f1.x) + (f2.x + f3.x);
        sy += (f0.y + f1.y) + (f2.y + f3.y);
    }

    if (!act) return;
    float nrm = g_norm[gw];
    float2 f = feat[(size_t)gw * D2 + lane];
    float vx = 0.9f * sx * nrm + 0.1f * f.x;
    float vy = 0.9f * sy * nrm + 0.1f * f.y;
    if (LAST) {
        out_r[(size_t)gw * D2 + lane] = make_float2(vx, vy);
    } else {
        __half2* __restrict__ o = RB ? g_hnA : g_hnB;
        o[(size_t)gw * D2 + lane] = __floats2half2_rn(vx * nrm, vy * nrm);
    }
}

// positionwise FFN: rst = relu(h@w1+b1)@w2 + b2 + features
// one thread per node row; weights in shared; packed f32x2 FFMA (FFMA2).
// Also resets the grid-barrier counters for the next graph replay.
__global__ void k_ffn(const float* __restrict__ h,
                      const float* __restrict__ feat,
                      const float* __restrict__ w1, const float* __restrict__ b1,
                      const float* __restrict__ w2, const float* __restrict__ b2,
                      float* __restrict__ out) {
    if (blockIdx.x == 0 && threadIdx.x < 4) g_bars[threadIdx.x] = 0;

    __shared__ __align__(16) float s_w1[D * D];
    __shared__ __align__(16) float s_w2[D * D];
    __shared__ __align__(16) float s_b1[D];
    __shared__ __align__(16) float s_b2[D];
    for (int i = threadIdx.x; i < D * D; i += blockDim.x) {
        s_w1[i] = w1[i];
        s_w2[i] = w2[i];
    }
    if (threadIdx.x < D) {
        s_b1[threadIdx.x] = b1[threadIdx.x];
        s_b2[threadIdx.x] = b2[threadIdx.x];
    }
    __syncthreads();

    int node = blockIdx.x * blockDim.x + threadIdx.x;
    if (node >= NN) return;

    float hr[D];
    const float4* hrow = (const float4*)(h + (size_t)node * D);
#pragma unroll
    for (int c = 0; c < D / 4; c++) {
        float4 v = hrow[c];
        hr[c * 4 + 0] = v.x; hr[c * 4 + 1] = v.y;
        hr[c * 4 + 2] = v.z; hr[c * 4 + 3] = v.w;
    }

    unsigned long long acc[D / 2];
    const unsigned long long* b1p = (const unsigned long long*)s_b1;
#pragma unroll
    for (int j = 0; j < D / 2; j++) acc[j] = b1p[j];

#pragma unroll 2
    for (int k = 0; k < D; k++) {
        unsigned long long hkp = pk2(hr[k]);
        const ulonglong2* wrow = (const ulonglong2*)&s_w1[k * D];
#pragma unroll
        for (int jc = 0; jc < D / 4; jc++) {
            ulonglong2 w = wrow[jc];
            fma2(acc[2 * jc],     hkp, w.x);
            fma2(acc[2 * jc + 1], hkp, w.y);
        }
    }

    float mid[D];
#pragma unroll
    for (int j = 0; j < D / 2; j++) {
        float2 t = up2(acc[j]);
        mid[2 * j]     = fmaxf(t.x, 0.f);
        mid[2 * j + 1] = fmaxf(t.y, 0.f);
    }

    const unsigned long long* b2p = (const unsigned long long*)s_b2;
#pragma unroll
    for (int j = 0; j < D / 2; j++) acc[j] = b2p[j];

#pragma unroll 2
    for (int k = 0; k < D; k++) {
        unsigned long long mkp = pk2(mid[k]);
        const ulonglong2* wrow = (const ulonglong2*)&s_w2[k * D];
#pragma unroll
        for (int jc = 0; jc < D / 4; jc++) {
            ulonglong2 w = wrow[jc];
            fma2(acc[2 * jc],     mkp, w.x);
            fma2(acc[2 * jc + 1], mkp, w.y);
        }
    }

    const float4* frow = (const float4*)(feat + (size_t)node * D);
    float4* orow = (float4*)(out + (size_t)node * D);
#pragma unroll
    for (int jc = 0; jc < D / 4; jc++) {
        float2 t0 = up2(acc[2 * jc]);
        float2 t1 = up2(acc[2 * jc + 1]);
        float4 f = frow[jc];
        orow[jc] = make_float4(t0.x + f.x, t0.y + f.y, t1.x + f.z, t1.y + f.w);
    }
}

// ---------------------------------------------------------------------
extern "C" void kernel_launch(void* const* d_in, const int* in_sizes, int n_in,
                              void* d_out, int out_size) {
    const float* feat = (const float*)d_in[0];
    const int*   src  = (const int*)d_in[1];
    const int*   dst  = (const int*)d_in[2];
    const float* w1   = (const float*)d_in[3];
    const float* b1   = (const float*)d_in[4];
    const float* w2   = (const float*)d_in[5];
    const float* b2   = (const float*)d_in[6];
    float* out = (float*)d_out;

    float* out_rst = out;                    // first output: rst [NN, D]
    float* out_r   = out + (size_t)NN * D;   // second output: r  [NN, D]

    const int T = 256;
    int gW = (NN * 32 + T - 1) / T;          // warp-per-node grid

    // occupancy-sized co-resident grids for the barrier kernels
    int dev = 0, sms = 0, o1 = 0, o2 = 0;
    cudaGetDevice(&dev);
    cudaDeviceGetAttribute(&sms, cudaDevAttrMultiProcessorCount, dev);
    cudaOccupancyMaxActiveBlocksPerMultiprocessor(&o1, k_build1, T, 0);
    cudaOccupancyMaxActiveBlocksPerMultiprocessor(&o2, k_build2, T, 0);
    if (o1 < 1) o1 = 1;
    if (o2 < 1) o2 = 1;
    int nb1 = sms * o1;
    int nb2 = sms * o2;

    // ---- CSR build: exactly 3 launches (k_prop hop0 = 4th -> ncu-profiled) ----
    k_build1<<<nb1, T>>>(dst, nb1);
    k_scan_all<<<SCAN_BLKS, 1024>>>();
    k_build2<<<nb2, T>>>(src, dst, (const float2*)feat, nb2);

    // ---- propagation ----
    for (int hop = 0; hop < HOPS; hop++) {
        int rb = hop & 1;
        if (hop == HOPS - 1) {
            if (rb) k_prop<1, 1><<<gW, T>>>((const float2*)feat, (float2*)out_r);
            else    k_prop<1, 0><<<gW, T>>>((const float2*)feat, (float2*)out_r);
        } else {
            if (rb) k_prop<0, 1><<<gW, T>>>((const float2*)feat, (float2*)out_r);
            else    k_prop<0, 0><<<gW, T>>>((const float2*)feat, (float2*)out_r);
        }
    }

    // ---- FFN + residual (also resets barrier counters for next replay) ----
    const int TF = 128;
    k_ffn<<<(NN + TF - 1) / TF, TF>>>(out_r, feat, w1, b1, w2, b2, out_rst);
}

// round 15
// speedup vs baseline: 1.1039x; 1.1039x over previous
#include <cuda_runtime.h>
#include <cuda_fp16.h>

#define NN 100000
#define NE 1600000
#define NE_PAD (NE + 3 * NN)      // segments padded to multiples of 4
#define D  48
#define D2 24                     // half2 chunks per feature row (96B packed)
#define HOPS 10
#define SCAN_BLKS ((NN + 1023) / 1024)   // 98

// ---- scratch (static device globals; no runtime allocation allowed) ----
__device__ int     g_degi[NN];
__device__ float   g_norm[NN];
__device__ int     g_offs[NN + 1];
__device__ int     g_bsum[128];
__device__ int     g_cursor[NN];
__device__ __align__(16) int g_csrc[NE_PAD];            // CSR src by dst (pad = NN)
__device__ __align__(16) __half2 g_hnA[(NN + 1) * D2];  // h*norm ping (row NN zeros)
__device__ __align__(16) __half2 g_hnB[(NN + 1) * D2];  // h*norm pong

// ---- packed f32x2 helpers (FFMA2: PTX-only on sm_103a) ----
__device__ __forceinline__ unsigned long long pk2(float x) {
    unsigned long long r;
    asm("mov.b64 %0, {%1, %1};" : "=l"(r) : "f"(x));
    return r;
}
__device__ __forceinline__ void fma2(unsigned long long& d,
                                     unsigned long long a, unsigned long long b) {
    asm("fma.rn.f32x2 %0, %1, %2, %0;" : "+l"(d) : "l"(a), "l"(b));
}
__device__ __forceinline__ float2 up2(unsigned long long v) {
    float x, y;
    asm("mov.b64 {%0, %1}, %2;" : "=f"(x), "=f"(y) : "l"(v));
    return make_float2(x, y);
}

// ---------------------------------------------------------------------
__global__ void k_zero_deg() {
    int i = blockIdx.x * blockDim.x + threadIdx.x;
    if (i < NN) g_degi[i] = 0;
}

__global__ void k_hist(const int* __restrict__ dst) {
    int e = blockIdx.x * blockDim.x + threadIdx.x;
    if (e < NE) atomicAdd(&g_degi[dst[e]], 1);
}

// inclusive scan of degrees padded to multiples of 4
__global__ void k_scan1() {
    __shared__ int sh[1024];
    int tid = threadIdx.x;
    int i = blockIdx.x * 1024 + tid;
    sh[tid] = (i < NN) ? ((g_degi[i] + 3) & ~3) : 0;
    __syncthreads();
#pragma unroll
    for (int off = 1; off < 1024; off <<= 1) {
        int t = (tid >= off) ? sh[tid - off] : 0;
        __syncthreads();
        sh[tid] += t;
        __syncthreads();
    }
    if (i < NN) g_offs[i + 1] = sh[tid];
    if (tid == 1023) g_bsum[blockIdx.x] = sh[1023];
}

// finalize offs (each block redundantly scans the 98 block sums in shared);
// fused norm + cursor
__global__ void k_scan3() {
    __shared__ int sb[128];
    int tid = threadIdx.x;
    if (tid < 128) {
        int v = (tid < SCAN_BLKS) ? g_bsum[tid] : 0;
        sb[tid] = v;
    }
    __syncthreads();
    if (tid < 128) {
        int v = sb[tid];
#pragma unroll
        for (int off = 1; off < 128; off <<= 1) {
            int u = (tid >= off) ? sb[tid - off] : 0;
            __syncthreads();
            sb[tid] += u;
            __syncthreads();
        }
        sb[tid] -= v;   // exclusive
    } else {
#pragma unroll
        for (int off = 1; off < 128; off <<= 1) { __syncthreads(); __syncthreads(); }
    }
    __syncthreads();

    int i = blockIdx.x * blockDim.x + tid;
    if (i > NN) return;
    int o;
    if (i == 0) { g_offs[0] = 0; o = 0; }
    else        { o = g_offs[i] + sb[(i - 1) >> 10]; g_offs[i] = o; }
    if (i < NN) {
        g_cursor[i] = o;
        g_norm[i] = rsqrtf(fmaxf((float)g_degi[i], 1.0f));
    }
}

__global__ void k_scatter(const int* __restrict__ src, const int* __restrict__ dst) {
    int e = blockIdx.x * blockDim.x + threadIdx.x;
    if (e >= NE) return;
    int pos = atomicAdd(&g_cursor[dst[e]], 1);
    g_csrc[pos] = src[e];
}

// fused: (a) fill segment tails (<=3 per node) with dummy index NN,
//        (b) hnA = half2(features * norm), zero dummy row NN in both buffers
__global__ void k_initpad(const float2* __restrict__ feat) {
    int i = blockIdx.x * blockDim.x + threadIdx.x;
    if (i < NN) {
        int p = g_cursor[i];
        int e = g_offs[i + 1];
        for (; p < e; p++) g_csrc[p] = NN;
    }
    if (i >= (NN + 1) * D2) return;
    int node = i / D2;
    if (node == NN) {
        g_hnA[i] = __floats2half2_rn(0.f, 0.f);
        g_hnB[i] = __floats2half2_rn(0.f, 0.f);
        return;
    }
    float n = g_norm[node];
    float2 f = feat[i];
    g_hnA[i] = __floats2half2_rn(f.x * n, f.y * n);
}

// One warp per destination node; lanes 0..23 own one half2 each of the
// packed 96B row. 4 independent row loads per iteration. ISSUE-BOUND fix:
// sum edge PAIRS in fp16 (HADD2) before converting -> 2 HADD2 + 4 cvt +
// 4 FADD per iter instead of 8 cvt + 8 FADD. fp32 accumulation across
// pairs; fused APPNP combine + renorm epilogue. RB: 0 = read A write B.
template <int LAST, int RB>
__global__ void __launch_bounds__(256) k_prop(const float2* __restrict__ feat,
                                              float2* __restrict__ out_r) {
    int gw = (blockIdx.x * blockDim.x + threadIdx.x) >> 5;
    if (gw >= NN) return;
    int lane = threadIdx.x & 31;
    bool act = lane < D2;
    int idx = act ? lane : 0;

    const __half2* __restrict__ hn = RB ? g_hnB : g_hnA;
    int beg = g_offs[gw];
    int end = g_offs[gw + 1];

    float sx = 0.f, sy = 0.f;
    for (int e = beg; e < end; e += 4) {
        int4 ss = __ldg((const int4*)&g_csrc[e]);
        __half2 v0 = __ldg(&hn[(size_t)ss.x * D2 + idx]);
        __half2 v1 = __ldg(&hn[(size_t)ss.y * D2 + idx]);
        __half2 v2 = __ldg(&hn[(size_t)ss.z * D2 + idx]);
        __half2 v3 = __ldg(&hn[(size_t)ss.w * D2 + idx]);
        __half2 s01 = __hadd2(v0, v1);        // fp16 pairwise sums
        __half2 s23 = __hadd2(v2, v3);
        float2 f01 = __half22float2(s01);
        float2 f23 = __half22float2(s23);
        sx += f01.x + f23.x;
        sy += f01.y + f23.y;
    }

    if (!act) return;
    float nrm = g_norm[gw];
    float2 f = feat[(size_t)gw * D2 + lane];
    float vx = 0.9f * sx * nrm + 0.1f * f.x;
    float vy = 0.9f * sy * nrm + 0.1f * f.y;
    if (LAST) {
        out_r[(size_t)gw * D2 + lane] = make_float2(vx, vy);
    } else {
        __half2* __restrict__ o = RB ? g_hnA : g_hnB;
        o[(size_t)gw * D2 + lane] = __floats2half2_rn(vx * nrm, vy * nrm);
    }
}

// positionwise FFN: rst = relu(h@w1+b1)@w2 + b2 + features
// one thread per node row; weights in shared; packed f32x2 FFMA (FFMA2)
__global__ void k_ffn(const float* __restrict__ h,
                      const float* __restrict__ feat,
                      const float* __restrict__ w1, const float* __restrict__ b1,
                      const float* __restrict__ w2, const float* __restrict__ b2,
                      float* __restrict__ out) {
    __shared__ __align__(16) float s_w1[D * D];
    __shared__ __align__(16) float s_w2[D * D];
    __shared__ __align__(16) float s_b1[D];
    __shared__ __align__(16) float s_b2[D];
    for (int i = threadIdx.x; i < D * D; i += blockDim.x) {
        s_w1[i] = w1[i];
        s_w2[i] = w2[i];
    }
    if (threadIdx.x < D) {
        s_b1[threadIdx.x] = b1[threadIdx.x];
        s_b2[threadIdx.x] = b2[threadIdx.x];
    }
    __syncthreads();

    int node = blockIdx.x * blockDim.x + threadIdx.x;
    if (node >= NN) return;

    float hr[D];
    const float4* hrow = (const float4*)(h + (size_t)node * D);
#pragma unroll
    for (int c = 0; c < D / 4; c++) {
        float4 v = hrow[c];
        hr[c * 4 + 0] = v.x; hr[c * 4 + 1] = v.y;
        hr[c * 4 + 2] = v.z; hr[c * 4 + 3] = v.w;
    }

    unsigned long long acc[D / 2];
    const unsigned long long* b1p = (const unsigned long long*)s_b1;
#pragma unroll
    for (int j = 0; j < D / 2; j++) acc[j] = b1p[j];

#pragma unroll 2
    for (int k = 0; k < D; k++) {
        unsigned long long hkp = pk2(hr[k]);
        const ulonglong2* wrow = (const ulonglong2*)&s_w1[k * D];
#pragma unroll
        for (int jc = 0; jc < D / 4; jc++) {
            ulonglong2 w = wrow[jc];
            fma2(acc[2 * jc],     hkp, w.x);
            fma2(acc[2 * jc + 1], hkp, w.y);
        }
    }

    float mid[D];
#pragma unroll
    for (int j = 0; j < D / 2; j++) {
        float2 t = up2(acc[j]);
        mid[2 * j]     = fmaxf(t.x, 0.f);
        mid[2 * j + 1] = fmaxf(t.y, 0.f);
    }

    const unsigned long long* b2p = (const unsigned long long*)s_b2;
#pragma unroll
    for (int j = 0; j < D / 2; j++) acc[j] = b2p[j];

#pragma unroll 2
    for (int k = 0; k < D; k++) {
        unsigned long long mkp = pk2(mid[k]);
        const ulonglong2* wrow = (const ulonglong2*)&s_w2[k * D];
#pragma unroll
        for (int jc = 0; jc < D / 4; jc++) {
            ulonglong2 w = wrow[jc];
            fma2(acc[2 * jc],     mkp, w.x);
            fma2(acc[2 * jc + 1], mkp, w.y);
        }
    }

    const float4* frow = (const float4*)(feat + (size_t)node * D);
    float4* orow = (float4*)(out + (size_t)node * D);
#pragma unroll
    for (int jc = 0; jc < D / 4; jc++) {
        float2 t0 = up2(acc[2 * jc]);
        float2 t1 = up2(acc[2 * jc + 1]);
        float4 f = frow[jc];
        orow[jc] = make_float4(t0.x + f.x, t0.y + f.y, t1.x + f.z, t1.y + f.w);
    }
}

// ---------------------------------------------------------------------
extern "C" void kernel_launch(void* const* d_in, const int* in_sizes, int n_in,
                              void* d_out, int out_size) {
    const float* feat = (const float*)d_in[0];
    const int*   src  = (const int*)d_in[1];
    const int*   dst  = (const int*)d_in[2];
    const float* w1   = (const float*)d_in[3];
    const float* b1   = (const float*)d_in[4];
    const float* w2   = (const float*)d_in[5];
    const float* b2   = (const float*)d_in[6];
    float* out = (float*)d_out;

    float* out_rst = out;                    // first output: rst [NN, D]
    float* out_r   = out + (size_t)NN * D;   // second output: r  [NN, D]

    const int T = 256;
    int gN  = (NN + T - 1) / T;
    int gE  = (NE + T - 1) / T;
    int gI  = ((NN + 1) * D2 + T - 1) / T;
    int gW  = (NN * 32 + T - 1) / T;         // warp-per-node grid

    // ---- CSR build (segments padded to multiples of 4) ----
    k_zero_deg<<<gN, T>>>();
    k_hist<<<gE, T>>>(dst);
    k_scan1<<<SCAN_BLKS, 1024>>>();
    k_scan3<<<(NN + 1 + T - 1) / T, T>>>();
    k_scatter<<<gE, T>>>(src, dst);
    k_initpad<<<gI, T>>>((const float2*)feat);

    // ---- propagation ----
    for (int hop = 0; hop < HOPS; hop++) {
        int rb = hop & 1;
        if (hop == HOPS - 1) {
            if (rb) k_prop<1, 1><<<gW, T>>>((const float2*)feat, (float2*)out_r);
            else    k_prop<1, 0><<<gW, T>>>((const float2*)feat, (float2*)out_r);
        } else {
            if (rb) k_prop<0, 1><<<gW, T>>>((const float2*)feat, (float2*)out_r);
            else    k_prop<0, 0><<<gW, T>>>((const float2*)feat, (float2*)out_r);
        }
    }

    // ---- FFN + residual ----
    const int TF = 128;
    k_ffn<<<(NN + TF - 1) / TF, TF>>>(out_r, feat, w1, b1, w2, b2, out_rst);
}

// round 16
// speedup vs baseline: 1.1301x; 1.0237x over previous
#include <cuda_runtime.h>
#include <cuda_fp16.h>

#define NN 100000
#define NE 1600000
#define NE_PAD (NE + 3 * NN)      // segments padded to multiples of 4
#define D  48
#define D2 24                     // half2 chunks per feature row (96B packed)
#define HOPS 10
#define SCAN_BLKS ((NN + 1023) / 1024)   // 98

// ---- scratch (static device globals; no runtime allocation allowed) ----
__device__ int     g_degi[NN];
__device__ float   g_norm[NN];
__device__ int     g_offs[NN + 1];
__device__ int     g_bsum[128];
__device__ int     g_cursor[NN];
__device__ __align__(16) int g_csrc[NE_PAD];            // CSR src by dst (pad = NN)
__device__ __align__(16) __half2 g_hnA[(NN + 1) * D2];  // h*norm ping (row NN zeros)
__device__ __align__(16) __half2 g_hnB[(NN + 1) * D2];  // h*norm pong

// ---- packed f32x2 helpers (FFMA2: PTX-only on sm_103a) ----
__device__ __forceinline__ unsigned long long pk2(float x) {
    unsigned long long r;
    asm("mov.b64 %0, {%1, %1};" : "=l"(r) : "f"(x));
    return r;
}
__device__ __forceinline__ void fma2(unsigned long long& d,
                                     unsigned long long a, unsigned long long b) {
    asm("fma.rn.f32x2 %0, %1, %2, %0;" : "+l"(d) : "l"(a), "l"(b));
}
__device__ __forceinline__ float2 up2(unsigned long long v) {
    float x, y;
    asm("mov.b64 {%0, %1}, %2;" : "=f"(x), "=f"(y) : "l"(v));
    return make_float2(x, y);
}

// ---------------------------------------------------------------------
__global__ void k_zero_deg() {
    int i = blockIdx.x * blockDim.x + threadIdx.x;
    if (i < NN) g_degi[i] = 0;
}

__global__ void k_hist(const int* __restrict__ dst) {
    int e = blockIdx.x * blockDim.x + threadIdx.x;
    if (e < NE) atomicAdd(&g_degi[dst[e]], 1);
}

// inclusive scan of degrees padded to multiples of 4
__global__ void k_scan1() {
    __shared__ int sh[1024];
    int tid = threadIdx.x;
    int i = blockIdx.x * 1024 + tid;
    sh[tid] = (i < NN) ? ((g_degi[i] + 3) & ~3) : 0;
    __syncthreads();
#pragma unroll
    for (int off = 1; off < 1024; off <<= 1) {
        int t = (tid >= off) ? sh[tid - off] : 0;
        __syncthreads();
        sh[tid] += t;
        __syncthreads();
    }
    if (i < NN) g_offs[i + 1] = sh[tid];
    if (tid == 1023) g_bsum[blockIdx.x] = sh[1023];
}

// finalize offs (each block redundantly scans the 98 block sums in shared);
// fused norm + cursor
__global__ void k_scan3() {
    __shared__ int sb[128];
    int tid = threadIdx.x;
    if (tid < 128) {
        int v = (tid < SCAN_BLKS) ? g_bsum[tid] : 0;
        sb[tid] = v;
    }
    __syncthreads();
    if (tid < 128) {
        int v = sb[tid];
#pragma unroll
        for (int off = 1; off < 128; off <<= 1) {
            int u = (tid >= off) ? sb[tid - off] : 0;
            __syncthreads();
            sb[tid] += u;
            __syncthreads();
        }
        sb[tid] -= v;   // exclusive
    } else {
#pragma unroll
        for (int off = 1; off < 128; off <<= 1) { __syncthreads(); __syncthreads(); }
    }
    __syncthreads();

    int i = blockIdx.x * blockDim.x + tid;
    if (i > NN) return;
    int o;
    if (i == 0) { g_offs[0] = 0; o = 0; }
    else        { o = g_offs[i] + sb[(i - 1) >> 10]; g_offs[i] = o; }
    if (i < NN) {
        g_cursor[i] = o;
        g_norm[i] = rsqrtf(fmaxf((float)g_degi[i], 1.0f));
    }
}

__global__ void k_scatter(const int* __restrict__ src, const int* __restrict__ dst) {
    int e = blockIdx.x * blockDim.x + threadIdx.x;
    if (e >= NE) return;
    int pos = atomicAdd(&g_cursor[dst[e]], 1);
    g_csrc[pos] = src[e];
}

// fused: (a) fill segment tails (<=3 per node) with dummy index NN,
//        (b) hnA = half2(features * norm), zero dummy row NN in both buffers
__global__ void k_initpad(const float2* __restrict__ feat) {
    int i = blockIdx.x * blockDim.x + threadIdx.x;
    if (i < NN) {
        int p = g_cursor[i];
        int e = g_offs[i + 1];
        for (; p < e; p++) g_csrc[p] = NN;
    }
    if (i >= (NN + 1) * D2) return;
    int node = i / D2;
    if (node == NN) {
        g_hnA[i] = __floats2half2_rn(0.f, 0.f);
        g_hnB[i] = __floats2half2_rn(0.f, 0.f);
        return;
    }
    float n = g_norm[node];
    float2 f = feat[i];
    g_hnA[i] = __floats2half2_rn(f.x * n, f.y * n);
}

// One warp per destination node; lanes 0..23 own one half2 each of the
// packed 96B row. 4 independent row loads per iteration. ISSUE-BOUND:
// full 4-way fp16 tree (3 HADD2) then ONE half2->float2 convert + 2 FADD
// per iteration (was 2 HADD2 + 4 cvt + 4 FADD). fp32 accumulation across
// iterations; fused APPNP combine + renorm epilogue. RB: 0 = read A write B.
template <int LAST, int RB>
__global__ void __launch_bounds__(256) k_prop(const float2* __restrict__ feat,
                                              float2* __restrict__ out_r) {
    int gw = (blockIdx.x * blockDim.x + threadIdx.x) >> 5;
    if (gw >= NN) return;
    int lane = threadIdx.x & 31;
    bool act = lane < D2;
    int idx = act ? lane : 0;

    const __half2* __restrict__ hn = RB ? g_hnB : g_hnA;
    int beg = g_offs[gw];
    int end = g_offs[gw + 1];

    float sx = 0.f, sy = 0.f;
    for (int e = beg; e < end; e += 4) {
        int4 ss = __ldg((const int4*)&g_csrc[e]);
        __half2 v0 = __ldg(&hn[(size_t)ss.x * D2 + idx]);
        __half2 v1 = __ldg(&hn[(size_t)ss.y * D2 + idx]);
        __half2 v2 = __ldg(&hn[(size_t)ss.z * D2 + idx]);
        __half2 v3 = __ldg(&hn[(size_t)ss.w * D2 + idx]);
        __half2 s = __hadd2(__hadd2(v0, v1), __hadd2(v2, v3));  // 4-way fp16 tree
        float2 fq = __half22float2(s);
        sx += fq.x;
        sy += fq.y;
    }

    if (!act) return;
    float nrm = g_norm[gw];
    float2 f = feat[(size_t)gw * D2 + lane];
    float vx = 0.9f * sx * nrm + 0.1f * f.x;
    float vy = 0.9f * sy * nrm + 0.1f * f.y;
    if (LAST) {
        out_r[(size_t)gw * D2 + lane] = make_float2(vx, vy);
    } else {
        __half2* __restrict__ o = RB ? g_hnA : g_hnB;
        o[(size_t)gw * D2 + lane] = __floats2half2_rn(vx * nrm, vy * nrm);
    }
}

// positionwise FFN: rst = relu(h@w1+b1)@w2 + b2 + features
// one thread per node row; weights in shared; packed f32x2 FFMA (FFMA2)
__global__ void k_ffn(const float* __restrict__ h,
                      const float* __restrict__ feat,
                      const float* __restrict__ w1, const float* __restrict__ b1,
                      const float* __restrict__ w2, const float* __restrict__ b2,
                      float* __restrict__ out) {
    __shared__ __align__(16) float s_w1[D * D];
    __shared__ __align__(16) float s_w2[D * D];
    __shared__ __align__(16) float s_b1[D];
    __shared__ __align__(16) float s_b2[D];
    for (int i = threadIdx.x; i < D * D; i += blockDim.x) {
        s_w1[i] = w1[i];
        s_w2[i] = w2[i];
    }
    if (threadIdx.x < D) {
        s_b1[threadIdx.x] = b1[threadIdx.x];
        s_b2[threadIdx.x] = b2[threadIdx.x];
    }
    __syncthreads();

    int node = blockIdx.x * blockDim.x + threadIdx.x;
    if (node >= NN) return;

    float hr[D];
    const float4* hrow = (const float4*)(h + (size_t)node * D);
#pragma unroll
    for (int c = 0; c < D / 4; c++) {
        float4 v = hrow[c];
        hr[c * 4 + 0] = v.x; hr[c * 4 + 1] = v.y;
        hr[c * 4 + 2] = v.z; hr[c * 4 + 3] = v.w;
    }

    unsigned long long acc[D / 2];
    const unsigned long long* b1p = (const unsigned long long*)s_b1;
#pragma unroll
    for (int j = 0; j < D / 2; j++) acc[j] = b1p[j];

#pragma unroll 2
    for (int k = 0; k < D; k++) {
        unsigned long long hkp = pk2(hr[k]);
        const ulonglong2* wrow = (const ulonglong2*)&s_w1[k * D];
#pragma unroll
        for (int jc = 0; jc < D / 4; jc++) {
            ulonglong2 w = wrow[jc];
            fma2(acc[2 * jc],     hkp, w.x);
            fma2(acc[2 * jc + 1], hkp, w.y);
        }
    }

    float mid[D];
#pragma unroll
    for (int j = 0; j < D / 2; j++) {
        float2 t = up2(acc[j]);
        mid[2 * j]     = fmaxf(t.x, 0.f);
        mid[2 * j + 1] = fmaxf(t.y, 0.f);
    }

    const unsigned long long* b2p = (const unsigned long long*)s_b2;
#pragma unroll
    for (int j = 0; j < D / 2; j++) acc[j] = b2p[j];

#pragma unroll 2
    for (int k = 0; k < D; k++) {
        unsigned long long mkp = pk2(mid[k]);
        const ulonglong2* wrow = (const ulonglong2*)&s_w2[k * D];
#pragma unroll
        for (int jc = 0; jc < D / 4; jc++) {
            ulonglong2 w = wrow[jc];
            fma2(acc[2 * jc],     mkp, w.x);
            fma2(acc[2 * jc + 1], mkp, w.y);
        }
    }

    const float4* frow = (const float4*)(feat + (size_t)node * D);
    float4* orow = (float4*)(out + (size_t)node * D);
#pragma unroll
    for (int jc = 0; jc < D / 4; jc++) {
        float2 t0 = up2(acc[2 * jc]);
        float2 t1 = up2(acc[2 * jc + 1]);
        float4 f = frow[jc];
        orow[jc] = make_float4(t0.x + f.x, t0.y + f.y, t1.x + f.z, t1.y + f.w);
    }
}

// ---------------------------------------------------------------------
extern "C" void kernel_launch(void* const* d_in, const int* in_sizes, int n_in,
                              void* d_out, int out_size) {
    const float* feat = (const float*)d_in[0];
    const int*   src  = (const int*)d_in[1];
    const int*   dst  = (const int*)d_in[2];
    const float* w1   = (const float*)d_in[3];
    const float* b1   = (const float*)d_in[4];
    const float* w2   = (const float*)d_in[5];
    const float* b2   = (const float*)d_in[6];
    float* out = (float*)d_out;

    float* out_rst = out;                    // first output: rst [NN, D]
    float* out_r   = out + (size_t)NN * D;   // second output: r  [NN, D]

    const int T = 256;
    int gN  = (NN + T - 1) / T;
    int gE  = (NE + T - 1) / T;
    int gI  = ((NN + 1) * D2 + T - 1) / T;
    int gW  = (NN * 32 + T - 1) / T;         // warp-per-node grid

    // ---- CSR build (segments padded to multiples of 4) ----
    k_zero_deg<<<gN, T>>>();
    k_hist<<<gE, T>>>(dst);
    k_scan1<<<SCAN_BLKS, 1024>>>();
    k_scan3<<<(NN + 1 + T - 1) / T, T>>>();
    k_scatter<<<gE, T>>>(src, dst);
    k_initpad<<<gI, T>>>((const float2*)feat);

    // ---- propagation ----
    for (int hop = 0; hop < HOPS; hop++) {
        int rb = hop & 1;
        if (hop == HOPS - 1) {
            if (rb) k_prop<1, 1><<<gW, T>>>((const float2*)feat, (float2*)out_r);
            else    k_prop<1, 0><<<gW, T>>>((const float2*)feat, (float2*)out_r);
        } else {
            if (rb) k_prop<0, 1><<<gW, T>>>((const float2*)feat, (float2*)out_r);
            else    k_prop<0, 0><<<gW, T>>>((const float2*)feat, (float2*)out_r);
        }
    }

    // ---- FFN + residual ----
    const int TF = 128;
    k_ffn<<<(NN + TF - 1) / TF, TF>>>(out_r, feat, w1, b1, w2, b2, out_rst);
}

// round 17
// speedup vs baseline: 1.1730x; 1.0379x over previous
#include <cuda_runtime.h>
#include <cuda_fp16.h>

#define NN 100000
#define NE 1600000
#define NE_PAD (NE + 3 * NN)      // segments padded to multiples of 4
#define D  48
#define D2 24                     // half2 chunks per feature row (96B packed)
#define HOPS 10
#define SCAN_BLKS ((NN + 1023) / 1024)   // 98

// ---- scratch (static device globals; no runtime allocation allowed) ----
__device__ int     g_degi[NN];
__device__ float   g_norm[NN];
__device__ int     g_offs[NN + 1];
__device__ int     g_bsum[128];
__device__ int     g_cursor[NN];
__device__ __align__(16) int g_csrc[NE_PAD];            // CSR src by dst (pad = NN)
__device__ __align__(16) __half2 g_hnA[(NN + 1) * D2];  // h*norm ping (row NN zeros)
__device__ __align__(16) __half2 g_hnB[(NN + 1) * D2];  // h*norm pong

// ---- packed f32x2 helpers (FFMA2: PTX-only on sm_103a) ----
__device__ __forceinline__ unsigned long long pk2(float x) {
    unsigned long long r;
    asm("mov.b64 %0, {%1, %1};" : "=l"(r) : "f"(x));
    return r;
}
__device__ __forceinline__ void fma2(unsigned long long& d,
                                     unsigned long long a, unsigned long long b) {
    asm("fma.rn.f32x2 %0, %1, %2, %0;" : "+l"(d) : "l"(a), "l"(b));
}
__device__ __forceinline__ float2 up2(unsigned long long v) {
    float x, y;
    asm("mov.b64 {%0, %1}, %2;" : "=f"(x), "=f"(y) : "l"(v));
    return make_float2(x, y);
}

// ---------------------------------------------------------------------
__global__ void k_zero_deg() {
    int i = blockIdx.x * blockDim.x + threadIdx.x;
    if (i < NN) g_degi[i] = 0;
}

__global__ void k_hist(const int* __restrict__ dst) {
    int e = blockIdx.x * blockDim.x + threadIdx.x;
    if (e < NE) atomicAdd(&g_degi[dst[e]], 1);
}

// inclusive scan of degrees padded to multiples of 4
__global__ void k_scan1() {
    __shared__ int sh[1024];
    int tid = threadIdx.x;
    int i = blockIdx.x * 1024 + tid;
    sh[tid] = (i < NN) ? ((g_degi[i] + 3) & ~3) : 0;
    __syncthreads();
#pragma unroll
    for (int off = 1; off < 1024; off <<= 1) {
        int t = (tid >= off) ? sh[tid - off] : 0;
        __syncthreads();
        sh[tid] += t;
        __syncthreads();
    }
    if (i < NN) g_offs[i + 1] = sh[tid];
    if (tid == 1023) g_bsum[blockIdx.x] = sh[1023];
}

// finalize offs (each block redundantly scans the 98 block sums in shared);
// fused norm + cursor
__global__ void k_scan3() {
    __shared__ int sb[128];
    int tid = threadIdx.x;
    if (tid < 128) {
        int v = (tid < SCAN_BLKS) ? g_bsum[tid] : 0;
        sb[tid] = v;
    }
    __syncthreads();
    if (tid < 128) {
        int v = sb[tid];
#pragma unroll
        for (int off = 1; off < 128; off <<= 1) {
            int u = (tid >= off) ? sb[tid - off] : 0;
            __syncthreads();
            sb[tid] += u;
            __syncthreads();
        }
        sb[tid] -= v;   // exclusive
    } else {
#pragma unroll
        for (int off = 1; off < 128; off <<= 1) { __syncthreads(); __syncthreads(); }
    }
    __syncthreads();

    int i = blockIdx.x * blockDim.x + tid;
    if (i > NN) return;
    int o;
    if (i == 0) { g_offs[0] = 0; o = 0; }
    else        { o = g_offs[i] + sb[(i - 1) >> 10]; g_offs[i] = o; }
    if (i < NN) {
        g_cursor[i] = o;
        g_norm[i] = rsqrtf(fmaxf((float)g_degi[i], 1.0f));
    }
}

__global__ void k_scatter(const int* __restrict__ src, const int* __restrict__ dst) {
    int e = blockIdx.x * blockDim.x + threadIdx.x;
    if (e >= NE) return;
    int pos = atomicAdd(&g_cursor[dst[e]], 1);
    g_csrc[pos] = src[e];
}

// fused: (a) fill segment tails (<=3 per node) with dummy index NN,
//        (b) hnA = half2(features * norm), zero dummy row NN in both buffers
__global__ void k_initpad(const float2* __restrict__ feat) {
    int i = blockIdx.x * blockDim.x + threadIdx.x;
    if (i < NN) {
        int p = g_cursor[i];
        int e = g_offs[i + 1];
        for (; p < e; p++) g_csrc[p] = NN;
    }
    if (i >= (NN + 1) * D2) return;
    int node = i / D2;
    if (node == NN) {
        g_hnA[i] = __floats2half2_rn(0.f, 0.f);
        g_hnB[i] = __floats2half2_rn(0.f, 0.f);
        return;
    }
    float n = g_norm[node];
    float2 f = feat[i];
    g_hnA[i] = __floats2half2_rn(f.x * n, f.y * n);
}

// One warp per destination node; lanes 0..23 own one half2 each of the
// packed 96B row. 4 independent row loads per iteration; 4-way fp16 HADD2
// tree + one cvt + 2 FADD. ADDRESSING: lane offset folded into base pointer
// (hp = hn + idx) so each row address is a single IMAD.WIDE(ss, 96, hp);
// index pointer iterated, not recomputed. RB: 0 = read A write B.
template <int LAST, int RB>
__global__ void __launch_bounds__(256) k_prop(const float2* __restrict__ feat,
                                              float2* __restrict__ out_r) {
    int gw = (blockIdx.x * blockDim.x + threadIdx.x) >> 5;
    if (gw >= NN) return;
    int lane = threadIdx.x & 31;
    bool act = lane < D2;
    int idx = act ? lane : 0;

    const __half2* __restrict__ hp = (RB ? g_hnB : g_hnA) + idx;  // lane-folded base
    int beg = g_offs[gw];
    int end = g_offs[gw + 1];
    const int4* __restrict__ ip = (const int4*)&g_csrc[beg];
    int n4 = (end - beg) >> 2;

    float sx = 0.f, sy = 0.f;
    for (int t = 0; t < n4; t++) {
        int4 ss = __ldg(ip + t);
        __half2 v0 = __ldg(hp + (size_t)ss.x * D2);
        __half2 v1 = __ldg(hp + (size_t)ss.y * D2);
        __half2 v2 = __ldg(hp + (size_t)ss.z * D2);
        __half2 v3 = __ldg(hp + (size_t)ss.w * D2);
        __half2 s = __hadd2(__hadd2(v0, v1), __hadd2(v2, v3));  // 4-way fp16 tree
        float2 fq = __half22float2(s);
        sx += fq.x;
        sy += fq.y;
    }

    if (!act) return;
    float nrm = g_norm[gw];
    float2 f = feat[(size_t)gw * D2 + lane];
    float vx = 0.9f * sx * nrm + 0.1f * f.x;
    float vy = 0.9f * sy * nrm + 0.1f * f.y;
    if (LAST) {
        out_r[(size_t)gw * D2 + lane] = make_float2(vx, vy);
    } else {
        __half2* __restrict__ o = RB ? g_hnA : g_hnB;
        o[(size_t)gw * D2 + lane] = __floats2half2_rn(vx * nrm, vy * nrm);
    }
}

// positionwise FFN: rst = relu(h@w1+b1)@w2 + b2 + features
// one thread per node row; weights in shared; packed f32x2 FFMA (FFMA2)
__global__ void k_ffn(const float* __restrict__ h,
                      const float* __restrict__ feat,
                      const float* __restrict__ w1, const float* __restrict__ b1,
                      const float* __restrict__ w2, const float* __restrict__ b2,
                      float* __restrict__ out) {
    __shared__ __align__(16) float s_w1[D * D];
    __shared__ __align__(16) float s_w2[D * D];
    __shared__ __align__(16) float s_b1[D];
    __shared__ __align__(16) float s_b2[D];
    for (int i = threadIdx.x; i < D * D; i += blockDim.x) {
        s_w1[i] = w1[i];
        s_w2[i] = w2[i];
    }
    if (threadIdx.x < D) {
        s_b1[threadIdx.x] = b1[threadIdx.x];
        s_b2[threadIdx.x] = b2[threadIdx.x];
    }
    __syncthreads();

    int node = blockIdx.x * blockDim.x + threadIdx.x;
    if (node >= NN) return;

    float hr[D];
    const float4* hrow = (const float4*)(h + (size_t)node * D);
#pragma unroll
    for (int c = 0; c < D / 4; c++) {
        float4 v = hrow[c];
        hr[c * 4 + 0] = v.x; hr[c * 4 + 1] = v.y;
        hr[c * 4 + 2] = v.z; hr[c * 4 + 3] = v.w;
    }

    unsigned long long acc[D / 2];
    const unsigned long long* b1p = (const unsigned long long*)s_b1;
#pragma unroll
    for (int j = 0; j < D / 2; j++) acc[j] = b1p[j];

#pragma unroll 2
    for (int k = 0; k < D; k++) {
        unsigned long long hkp = pk2(hr[k]);
        const ulonglong2* wrow = (const ulonglong2*)&s_w1[k * D];
#pragma unroll
        for (int jc = 0; jc < D / 4; jc++) {
            ulonglong2 w = wrow[jc];
            fma2(acc[2 * jc],     hkp, w.x);
            fma2(acc[2 * jc + 1], hkp, w.y);
        }
    }

    float mid[D];
#pragma unroll
    for (int j = 0; j < D / 2; j++) {
        float2 t = up2(acc[j]);
        mid[2 * j]     = fmaxf(t.x, 0.f);
        mid[2 * j + 1] = fmaxf(t.y, 0.f);
    }

    const unsigned long long* b2p = (const unsigned long long*)s_b2;
#pragma unroll
    for (int j = 0; j < D / 2; j++) acc[j] = b2p[j];

#pragma unroll 2
    for (int k = 0; k < D; k++) {
        unsigned long long mkp = pk2(mid[k]);
        const ulonglong2* wrow = (const ulonglong2*)&s_w2[k * D];
#pragma unroll
        for (int jc = 0; jc < D / 4; jc++) {
            ulonglong2 w = wrow[jc];
            fma2(acc[2 * jc],     mkp, w.x);
            fma2(acc[2 * jc + 1], mkp, w.y);
        }
    }

    const float4* frow = (const float4*)(feat + (size_t)node * D);
    float4* orow = (float4*)(out + (size_t)node * D);
#pragma unroll
    for (int jc = 0; jc < D / 4; jc++) {
        float2 t0 = up2(acc[2 * jc]);
        float2 t1 = up2(acc[2 * jc + 1]);
        float4 f = frow[jc];
        orow[jc] = make_float4(t0.x + f.x, t0.y + f.y, t1.x + f.z, t1.y + f.w);
    }
}

// ---------------------------------------------------------------------
extern "C" void kernel_launch(void* const* d_in, const int* in_sizes, int n_in,
                              void* d_out, int out_size) {
    const float* feat = (const float*)d_in[0];
    const int*   src  = (const int*)d_in[1];
    const int*   dst  = (const int*)d_in[2];
    const float* w1   = (const float*)d_in[3];
    const float* b1   = (const float*)d_in[4];
    const float* w2   = (const float*)d_in[5];
    const float* b2   = (const float*)d_in[6];
    float* out = (float*)d_out;

    float* out_rst = out;                    // first output: rst [NN, D]
    float* out_r   = out + (size_t)NN * D;   // second output: r  [NN, D]

    const int T = 256;
    int gN  = (NN + T - 1) / T;
    int gE  = (NE + T - 1) / T;
    int gI  = ((NN + 1) * D2 + T - 1) / T;
    int gW  = (NN * 32 + T - 1) / T;         // warp-per-node grid

    // ---- CSR build (segments padded to multiples of 4) ----
    k_zero_deg<<<gN, T>>>();
    k_hist<<<gE, T>>>(dst);
    k_scan1<<<SCAN_BLKS, 1024>>>();
    k_scan3<<<(NN + 1 + T - 1) / T, T>>>();
    k_scatter<<<gE, T>>>(src, dst);
    k_initpad<<<gI, T>>>((const float2*)feat);

    // ---- propagation ----
    for (int hop = 0; hop < HOPS; hop++) {
        int rb = hop & 1;
        if (hop == HOPS - 1) {
            if (rb) k_prop<1, 1><<<gW, T>>>((const float2*)feat, (float2*)out_r);
            else    k_prop<1, 0><<<gW, T>>>((const float2*)feat, (float2*)out_r);
        } else {
            if (rb) k_prop<0, 1><<<gW, T>>>((const float2*)feat, (float2*)out_r);
            else    k_prop<0, 0><<<gW, T>>>((const float2*)feat, (float2*)out_r);
        }
    }

    // ---- FFN + residual ----
    const int TF = 128;
    k_ffn<<<(NN + TF - 1) / TF, TF>>>(out_r, feat, w1, b1, w2, b2, out_rst);
}